// round 1
// baseline (speedup 1.0000x reference)
#include <cuda_runtime.h>

// Problem constants
#define BB 128
#define TT 2048
#define LL 8              // timesteps per chunk
#define CC (TT / LL)      // 256 chunks per batch
#define NM (BB * TT)      // 262144 matrices total
#define DT 0.02f

// Scratch: 32 floats per 4x4 complex matrix = [re[16], im[16]] = 8 float4 (128B, line-aligned)
__device__ __align__(128) float4 g_U[(size_t)NM * 8];        // 33.5 MB: all unitaries
__device__ __align__(128) float4 g_P[(size_t)BB * CC * 8];   // chunk products
__device__ __align__(128) float4 g_S[(size_t)BB * CC * 8];   // incoming state per chunk

// ---------------------------------------------------------------------------
// 4x4 complex matmul helpers (fully unrolled, 16 independent accumulators)
// z = x * y   (z must not alias x or y)
__device__ __forceinline__ void cmm(const float* __restrict__ xr, const float* __restrict__ xi,
                                    const float* __restrict__ yr, const float* __restrict__ yi,
                                    float* __restrict__ zr, float* __restrict__ zi) {
#pragma unroll
    for (int i = 0; i < 4; ++i) {
#pragma unroll
        for (int j = 0; j < 4; ++j) {
            float sr = 0.0f, si = 0.0f;
#pragma unroll
            for (int k = 0; k < 4; ++k) {
                float a = xr[i * 4 + k], bq = xi[i * 4 + k];
                float c = yr[k * 4 + j], d = yi[k * 4 + j];
                sr = fmaf(a, c, sr); sr = fmaf(-bq, d, sr);
                si = fmaf(a, d, si); si = fmaf(bq, c, si);
            }
            zr[i * 4 + j] = sr;
            zi[i * 4 + j] = si;
        }
    }
}

// z += x * y
__device__ __forceinline__ void cmma(const float* __restrict__ xr, const float* __restrict__ xi,
                                     const float* __restrict__ yr, const float* __restrict__ yi,
                                     float* __restrict__ zr, float* __restrict__ zi) {
#pragma unroll
    for (int i = 0; i < 4; ++i) {
#pragma unroll
        for (int j = 0; j < 4; ++j) {
            float sr = zr[i * 4 + j], si = zi[i * 4 + j];
#pragma unroll
            for (int k = 0; k < 4; ++k) {
                float a = xr[i * 4 + k], bq = xi[i * 4 + k];
                float c = yr[k * 4 + j], d = yi[k * 4 + j];
                sr = fmaf(a, c, sr); sr = fmaf(-bq, d, sr);
                si = fmaf(a, d, si); si = fmaf(bq, c, si);
            }
            zr[i * 4 + j] = sr;
            zi[i * 4 + j] = si;
        }
    }
}

__device__ __forceinline__ void ld_mat(const float4* __restrict__ p, float* r, float* m) {
#pragma unroll
    for (int q = 0; q < 4; ++q) {
        float4 v = p[q];
        r[4 * q + 0] = v.x; r[4 * q + 1] = v.y; r[4 * q + 2] = v.z; r[4 * q + 3] = v.w;
    }
#pragma unroll
    for (int q = 0; q < 4; ++q) {
        float4 v = p[4 + q];
        m[4 * q + 0] = v.x; m[4 * q + 1] = v.y; m[4 * q + 2] = v.z; m[4 * q + 3] = v.w;
    }
}

__device__ __forceinline__ void st_mat(float4* __restrict__ p, const float* r, const float* m) {
#pragma unroll
    for (int q = 0; q < 4; ++q)
        p[q] = make_float4(r[4 * q + 0], r[4 * q + 1], r[4 * q + 2], r[4 * q + 3]);
#pragma unroll
    for (int q = 0; q < 4; ++q)
        p[4 + q] = make_float4(m[4 * q + 0], m[4 * q + 1], m[4 * q + 2], m[4 * q + 3]);
}

__device__ __forceinline__ void cp_mat(float* __restrict__ dr, float* __restrict__ di,
                                       const float* sr, const float* si) {
#pragma unroll
    for (int e = 0; e < 16; ++e) { dr[e] = sr[e]; di[e] = si[e]; }
}

// ---------------------------------------------------------------------------
// K0: one thread per (b,t): U = expm(-i*dt*H) via degree-6 Taylor (Paterson-Stockmeyer)
__global__ void __launch_bounds__(128) k_expm(const float* __restrict__ hr_g,
                                              const float* __restrict__ hi_g) {
    int idx = blockIdx.x * blockDim.x + threadIdx.x;   // = b*TT + t
    if (idx >= NM) return;

    const float4* hr4 = reinterpret_cast<const float4*>(hr_g) + (size_t)idx * 4;
    const float4* hi4 = reinterpret_cast<const float4*>(hi_g) + (size_t)idx * 4;

    // A = -i*dt*(hr + i*hi) = dt*hi - i*dt*hr
    float ar[16], ai[16];
#pragma unroll
    for (int q = 0; q < 4; ++q) {
        float4 r = hr4[q], m = hi4[q];
        ar[4 * q + 0] =  DT * m.x; ar[4 * q + 1] =  DT * m.y;
        ar[4 * q + 2] =  DT * m.z; ar[4 * q + 3] =  DT * m.w;
        ai[4 * q + 0] = -DT * r.x; ai[4 * q + 1] = -DT * r.y;
        ai[4 * q + 2] = -DT * r.z; ai[4 * q + 3] = -DT * r.w;
    }

    float br[16], bi[16];               // A^2
    cmm(ar, ai, ar, ai, br, bi);
    float cr[16], ci[16];               // A^3
    cmm(br, bi, ar, ai, cr, ci);

    // M = I/6 + A/24 + A2/120 + A3/720
    float mr[16], mi[16];
#pragma unroll
    for (int e = 0; e < 16; ++e) {
        mr[e] = fmaf(1.0f / 24.0f, ar[e], fmaf(1.0f / 120.0f, br[e], (1.0f / 720.0f) * cr[e]));
        mi[e] = fmaf(1.0f / 24.0f, ai[e], fmaf(1.0f / 120.0f, bi[e], (1.0f / 720.0f) * ci[e]));
    }
    mr[0] += 1.0f / 6.0f; mr[5] += 1.0f / 6.0f; mr[10] += 1.0f / 6.0f; mr[15] += 1.0f / 6.0f;

    // E = I + A + A2/2  (into br/bi, A2 dead after)
#pragma unroll
    for (int e = 0; e < 16; ++e) {
        br[e] = fmaf(0.5f, br[e], ar[e]);
        bi[e] = fmaf(0.5f, bi[e], ai[e]);
    }
    br[0] += 1.0f; br[5] += 1.0f; br[10] += 1.0f; br[15] += 1.0f;

    // E += A3 * M
    cmma(cr, ci, mr, mi, br, bi);

    st_mat(g_U + (size_t)idx * 8, br, bi);
}

// ---------------------------------------------------------------------------
// K1: one thread per (b,chunk): product of LL unitaries (newest on the left)
__global__ void __launch_bounds__(128) k_chunk() {
    int idx = blockIdx.x * blockDim.x + threadIdx.x;   // = b*CC + c
    if (idx >= BB * CC) return;
    size_t ub = (size_t)idx * LL * 8;                  // b*TT + c*LL == idx*LL

    float pr[16], pi[16];
    ld_mat(g_U + ub, pr, pi);
    float ur[16], ui[16], tr[16], ti[16];
#pragma unroll
    for (int l = 1; l < LL; ++l) {
        ld_mat(g_U + ub + (size_t)l * 8, ur, ui);
        cmm(ur, ui, pr, pi, tr, ti);
        cp_mat(pr, pi, tr, ti);
    }
    st_mat(g_P + (size_t)idx * 8, pr, pi);
}

// ---------------------------------------------------------------------------
// K2: per-batch Kogge-Stone inclusive scan of chunk products, then emit
//     incoming state V_c = (P_{c-1}...P_0) * S0   (V_0 = S0)
#define SH_STRIDE 33   // pad to avoid 32-way bank conflicts

__global__ void __launch_bounds__(CC) k_scan(const float* __restrict__ s0r_g,
                                             const float* __restrict__ s0i_g) {
    __shared__ float sh[CC * SH_STRIDE];
    int b = blockIdx.x;
    int e = threadIdx.x;

    float pr[16], pi[16];
    ld_mat(g_P + ((size_t)b * CC + e) * 8, pr, pi);

    float qr[16], qi[16], tr[16], ti[16];
    for (int d = 1; d < CC; d <<= 1) {
        float* me = sh + e * SH_STRIDE;
#pragma unroll
        for (int k = 0; k < 16; ++k) { me[k] = pr[k]; me[16 + k] = pi[k]; }
        __syncthreads();
        if (e >= d) {
            const float* nb = sh + (e - d) * SH_STRIDE;
#pragma unroll
            for (int k = 0; k < 16; ++k) { qr[k] = nb[k]; qi[k] = nb[16 + k]; }
            cmm(pr, pi, qr, qi, tr, ti);   // newer-block * older-block
            cp_mat(pr, pi, tr, ti);
        }
        __syncthreads();
    }

    // publish inclusive prefixes, each thread fetches its left neighbor
    {
        float* me = sh + e * SH_STRIDE;
#pragma unroll
        for (int k = 0; k < 16; ++k) { me[k] = pr[k]; me[16 + k] = pi[k]; }
    }
    __syncthreads();

    // S0 for this batch
    float s0r[16], s0i[16];
    {
        const float4* r4 = reinterpret_cast<const float4*>(s0r_g) + (size_t)b * 4;
        const float4* i4 = reinterpret_cast<const float4*>(s0i_g) + (size_t)b * 4;
#pragma unroll
        for (int q = 0; q < 4; ++q) {
            float4 v = r4[q];
            s0r[4 * q + 0] = v.x; s0r[4 * q + 1] = v.y; s0r[4 * q + 2] = v.z; s0r[4 * q + 3] = v.w;
            float4 w = i4[q];
            s0i[4 * q + 0] = w.x; s0i[4 * q + 1] = w.y; s0i[4 * q + 2] = w.z; s0i[4 * q + 3] = w.w;
        }
    }

    float vr[16], vi[16];
    if (e == 0) {
        cp_mat(vr, vi, s0r, s0i);
    } else {
        const float* nb = sh + (e - 1) * SH_STRIDE;
#pragma unroll
        for (int k = 0; k < 16; ++k) { qr[k] = nb[k]; qi[k] = nb[16 + k]; }
        cmm(qr, qi, s0r, s0i, vr, vi);
    }
    st_mat(g_S + ((size_t)b * CC + e) * 8, vr, vi);
}

// ---------------------------------------------------------------------------
// K3: replay each chunk from its incoming state, stream all T states out.
// Output layout: [2, T, B, 4, 4] float32 (plane 0 = real, plane 1 = imag)
__global__ void __launch_bounds__(128) k_apply(float* __restrict__ out) {
    int idx = blockIdx.x * blockDim.x + threadIdx.x;   // = b*CC + c
    if (idx >= BB * CC) return;
    int b = idx / CC;
    int c = idx % CC;

    float sr[16], si[16];
    ld_mat(g_S + (size_t)idx * 8, sr, si);

    size_t ub = (size_t)idx * LL * 8;
    size_t t0 = (size_t)c * LL;
    float ur[16], ui[16], tr[16], ti[16];
    float4* outr_base = reinterpret_cast<float4*>(out);
    const size_t imag_off4 = (size_t)TT * BB * 4;      // in float4 units

#pragma unroll
    for (int l = 0; l < LL; ++l) {
        ld_mat(g_U + ub + (size_t)l * 8, ur, ui);
        cmm(ur, ui, sr, si, tr, ti);
        cp_mat(sr, si, tr, ti);

        size_t t = t0 + l;
        float4* outr = outr_base + (t * BB + b) * 4;
        float4* outi = outr + imag_off4;
#pragma unroll
        for (int q = 0; q < 4; ++q)
            outr[q] = make_float4(sr[4 * q + 0], sr[4 * q + 1], sr[4 * q + 2], sr[4 * q + 3]);
#pragma unroll
        for (int q = 0; q < 4; ++q)
            outi[q] = make_float4(si[4 * q + 0], si[4 * q + 1], si[4 * q + 2], si[4 * q + 3]);
    }
}

// ---------------------------------------------------------------------------
extern "C" void kernel_launch(void* const* d_in, const int* in_sizes, int n_in,
                              void* d_out, int out_size) {
    const float* h_real = (const float*)d_in[0];
    const float* h_imag = (const float*)d_in[1];
    const float* s_real = (const float*)d_in[2];
    const float* s_imag = (const float*)d_in[3];
    float* out = (float*)d_out;

    k_expm<<<NM / 128, 128>>>(h_real, h_imag);
    k_chunk<<<(BB * CC) / 128, 128>>>();
    k_scan<<<BB, CC>>>(s_real, s_imag);
    k_apply<<<(BB * CC) / 128, 128>>>(out);
}